// round 16
// baseline (speedup 1.0000x reference)
#include <cuda_runtime.h>
#include <cuda_bf16.h>
#include <cstdint>

#define NB_B 4096
#define ND 16
#define NM 4
#define NR 2048
#define NC 10
#define NDP1 17
#define MU 8.5f
#define LOG2E 1.4426950408889634f

typedef unsigned long long ull;

// quadratic-form weights, k-major: rows 0..15 = A (x^2), 16..31 = B (x), 32 = C
__device__ float    g_W[33 * NR];
__device__ float    g_psum[16 * NB_B];     // per r-block batch sums of f
// cons planes, mean-centered bf16x2, pair-interleaved:
__device__ uint4    g_consA[NR / 2];
__device__ uint4    g_consB[NR / 2];
__device__ uint2    g_consC[NR / 2];
__device__ float    g_norm_scratch[(size_t)NB_B * NR];  // fallback only

__device__ __forceinline__ ull pack2(float x, float y) {
    ull r;
    asm("mov.b64 %0, {%1, %2};" : "=l"(r) : "f"(x), "f"(y));
    return r;
}
__device__ __forceinline__ void unpack2(float& x, float& y, ull v) {
    asm("mov.b64 {%0, %1}, %2;" : "=f"(x), "=f"(y) : "l"(v));
}
__device__ __forceinline__ void ffma2(ull& d, ull a, ull b) {
    asm("fma.rn.f32x2 %0, %1, %2, %0;" : "+l"(d) : "l"(a), "l"(b));
}
__device__ __forceinline__ float ex2(float s) {
    float r;
    asm("ex2.approx.ftz.f32 %0, %1;" : "=f"(r) : "f"(s));
    return r;
}
__device__ __forceinline__ float bf16lo(unsigned w) {
    return __uint_as_float(w << 16);
}
__device__ __forceinline__ float bf16hi(unsigned w) {
    return __uint_as_float(w & 0xffff0000u);
}

// ---------------------------------------------------------------------------
// K0: prep. 128 blocks x 256 thr; 16 rules/block. Coalesced staging, then:
//  - all 256 threads (d, rl): quadratic coefficients A, B (coalesced writes)
//  - 80 threads: mean-centered bf16x2 cons plane sums
//  - 16 threads: C = sum_d A*c^2
// ---------------------------------------------------------------------------
__global__ __launch_bounds__(256) void prep_kernel(
    const float* __restrict__ cons, const int* __restrict__ rules,
    const float* __restrict__ centers, const float* __restrict__ widths) {
    __shared__ float sc[16 * NDP1 * NC];   // 10880 B
    __shared__ int   sr[16 * ND];
    __shared__ float sCc[16][17];

    const int tid = threadIdx.x;
    const int r0  = blockIdx.x * 16;

    const float* cbase = cons + (size_t)r0 * NDP1 * NC;
#pragma unroll
    for (int i = tid; i < 16 * NDP1 * NC; i += 256) sc[i] = cbase[i];
    sr[tid] = rules[r0 * ND + tid];        // exactly 256 ints
    __syncthreads();

    // W coefficients: thread (d = tid>>4, rl = tid&15)
    {
        const int d = tid >> 4, rl = tid & 15;
        const int m = sr[rl * ND + d];
        const float c  = centers[d * NM + m];
        const float wd = widths[d * NM + m];
        const float A2 = -0.5f * LOG2E / (wd * wd);
        const int r = r0 + rl;
        g_W[d * NR + r]        = A2;
        g_W[(16 + d) * NR + r] = -2.f * c * A2;
        sCc[rl][d] = A2 * c * c;
    }
    __syncthreads();

    if (tid < 80) {
        const int rl = tid / 5, p = tid % 5;
        const float* row = sc + rl * NDP1 * NC + 2 * p;
        float s0 = 0.f, s1 = 0.f;
#pragma unroll
        for (int j = 0; j < NDP1; ++j) {
            s0 += row[j * NC];
            s1 += row[j * NC + 1];
        }
        const int gw = r0 + rl, q = gw >> 1, r1 = gw & 1;
        __nv_bfloat162 h = __floats2bfloat162_rn(s0 - MU, s1 - MU);
        unsigned wb = *(unsigned*)&h;
        if (p == 0)      ((unsigned*)g_consA)[q * 4 + 0 + r1] = wb;
        else if (p == 1) ((unsigned*)g_consA)[q * 4 + 2 + r1] = wb;
        else if (p == 2) ((unsigned*)g_consB)[q * 4 + 0 + r1] = wb;
        else if (p == 3) ((unsigned*)g_consB)[q * 4 + 2 + r1] = wb;
        else             ((unsigned*)g_consC)[q * 2 + r1]     = wb;
    } else if (tid < 96) {
        const int rl = tid - 80;
        float s = 0.f;
#pragma unroll
        for (int d = 0; d < ND; ++d) s += sCc[rl][d];
        g_W[32 * NR + r0 + rl] = s;
    }
}

// ---------------------------------------------------------------------------
// K1: GEMM  S[128r x 64b] = W_tile(33x128) . X_tile(33x64), packed f32x2
// over rule pairs (W pairs load natively from k-major layout; X dup-packed,
// broadcast LDS). Lane owns 4 contiguous rules x 8 batches. Epilogue:
// f = exp2(s), fully coalesced STG.128 of unnormalized f, per-(rblock,b)
// batch sums -> g_psum. grid (64 bblocks, 16 rblocks).
// ---------------------------------------------------------------------------
__global__ __launch_bounds__(256, 4) void gemm_kernel(
    const float* __restrict__ x, float* __restrict__ f_out) {
    __shared__ __align__(16) ull   s_wp[33 * 64];  // W pairs: 16.9 KB
    __shared__ __align__(16) ull   s_xd[33 * 64];  // X dup-packed: 16.9 KB
    __shared__ float s_xs[64 * 17];                // raw x, padded

    const int tid  = threadIdx.x;
    const int w    = tid >> 5;
    const int lane = tid & 31;
    const int b0   = blockIdx.x * 64;
    const int rb   = blockIdx.y;

    const ull* gw = (const ull*)g_W;
#pragma unroll
    for (int i = tid; i < 33 * 64; i += 256) {
        int k = i >> 6, rp = i & 63;
        s_wp[i] = gw[k * (NR / 2) + rb * 64 + rp];
    }
#pragma unroll
    for (int i = tid; i < 64 * ND; i += 256) {
        int b = i >> 4, d = i & 15;
        s_xs[b * 17 + d] = x[(b0 + b) * ND + d];
    }
    __syncthreads();
#pragma unroll
    for (int i = tid; i < 33 * 64; i += 256) {
        int k = i >> 6, b = i & 63;
        float v;
        if (k < 16)      { float t = s_xs[b * 17 + k]; v = t * t; }
        else if (k < 32) { v = s_xs[b * 17 + k - 16]; }
        else             { v = 1.f; }
        s_xd[i] = pack2(v, v);
    }
    __syncthreads();

    ull acc[2][8];
#pragma unroll
    for (int i = 0; i < 2; ++i)
#pragma unroll
        for (int j = 0; j < 8; ++j) acc[i][j] = 0ull;

    for (int k = 0; k < 33; ++k) {
        ulonglong2 wf = *(const ulonglong2*)&s_wp[k * 64 + lane * 2];
#pragma unroll
        for (int jj = 0; jj < 4; ++jj) {
            ulonglong2 xp = *(const ulonglong2*)&s_xd[k * 64 + w * 8 + jj * 2];
            ffma2(acc[0][2 * jj],     wf.x, xp.x);
            ffma2(acc[1][2 * jj],     wf.y, xp.x);
            ffma2(acc[0][2 * jj + 1], wf.x, xp.y);
            ffma2(acc[1][2 * jj + 1], wf.y, xp.y);
        }
    }

    // epilogue: exp2, coalesced f store, batch sums
#pragma unroll
    for (int j = 0; j < 8; ++j) {
        const int b = b0 + w * 8 + j;
        float s0, s1, s2, s3;
        unpack2(s0, s1, acc[0][j]);
        unpack2(s2, s3, acc[1][j]);
        float f0 = ex2(s0), f1 = ex2(s1), f2 = ex2(s2), f3 = ex2(s3);
        *(float4*)(f_out + (size_t)b * NR + rb * 128 + lane * 4) =
            make_float4(f0, f1, f2, f3);
        float bs = (f0 + f1) + (f2 + f3);
#pragma unroll
        for (int off = 16; off > 0; off >>= 1)
            bs += __shfl_xor_sync(0xffffffffu, bs, off);
        if (lane == 0) g_psum[rb * NB_B + b] = bs;
    }
}

// ---------------------------------------------------------------------------
// K2: finalize. 256 blocks x 256 thr; warp = 2 batches (16 batches/block).
// cons planes staged ONCE per block (40 KB). Per warp: tot from psum,
// inv, sx/xext; one pass over f: normalize (LDG/STG.64) + GEMV from
// smem cons (batch-paired, conflict-free LDS); out.
// ---------------------------------------------------------------------------
__global__ __launch_bounds__(256) void finalize_kernel(
    const float* __restrict__ x,
    float* __restrict__ norm,
    float* __restrict__ xext_out,
    float* __restrict__ out,
    int write_xext) {
    __shared__ uint4 sA[NR / 2];   // 16 KB
    __shared__ uint4 sB[NR / 2];   // 16 KB
    __shared__ uint2 sC2[NR / 2];  // 8 KB

    const int tid  = threadIdx.x;
    const int w    = tid >> 5;
    const int lane = tid & 31;

#pragma unroll
    for (int i = tid; i < NR / 2; i += 256) {
        sA[i] = g_consA[i];
        sB[i] = g_consB[i];
        sC2[i] = g_consC[i];
    }
    __syncthreads();

    const int bA = blockIdx.x * 16 + w * 2;
    const int bB = bA + 1;

    // totals from psum partials
    float psA = (lane < 16) ? g_psum[lane * NB_B + bA] : 0.f;
    float psB = (lane < 16) ? g_psum[lane * NB_B + bB] : 0.f;
    // sx and xext
    float xA = (lane < ND) ? x[bA * ND + lane] : 0.f;
    float xB = (lane < ND) ? x[bB * ND + lane] : 0.f;
    if (write_xext) {
        if (lane < ND) {
            xext_out[bA * NDP1 + lane] = xA;
            xext_out[bB * NDP1 + lane] = xB;
        }
        if (lane == ND) {
            xext_out[bA * NDP1 + ND] = 1.f;
            xext_out[bB * NDP1 + ND] = 1.f;
        }
    }
    float totA = psA, totB = psB, sxA = xA, sxB = xB;
#pragma unroll
    for (int off = 16; off > 0; off >>= 1) {
        totA += __shfl_xor_sync(0xffffffffu, totA, off);
        totB += __shfl_xor_sync(0xffffffffu, totB, off);
        sxA  += __shfl_xor_sync(0xffffffffu, sxA, off);
        sxB  += __shfl_xor_sync(0xffffffffu, sxB, off);
    }
    sxA += 1.f;
    sxB += 1.f;
    const float invA = 1.f / (totA + 1e-9f);
    const float invB = 1.f / (totB + 1e-9f);

    float2* fA = (float2*)(norm + (size_t)bA * NR);
    float2* fB = (float2*)(norm + (size_t)bB * NR);

    float accA[NC], accB[NC];
#pragma unroll
    for (int c = 0; c < NC; ++c) { accA[c] = 0.f; accB[c] = 0.f; }

#pragma unroll 4
    for (int it = 0; it < 32; ++it) {
        const int q = it * 32 + lane;        // rule-pair index
        float2 vA = fA[q];
        float2 vB = fB[q];
        const float n0A = vA.x * invA, n1A = vA.y * invA;
        const float n0B = vB.x * invB, n1B = vB.y * invB;
        fA[q] = make_float2(n0A, n1A);       // normalized norm_fs
        fB[q] = make_float2(n0B, n1B);

        uint4 cA4 = sA[q];
        uint4 cB4 = sB[q];
        uint2 cc  = sC2[q];
        const unsigned we[5] = {cA4.x, cA4.z, cB4.x, cB4.z, cc.x};
        const unsigned wo[5] = {cA4.y, cA4.w, cB4.y, cB4.w, cc.y};
#pragma unroll
        for (int p = 0; p < 5; ++p) {
            const float celo = bf16lo(we[p]), cehi = bf16hi(we[p]);
            const float colo = bf16lo(wo[p]), cohi = bf16hi(wo[p]);
            accA[2 * p]     = fmaf(n0A, celo, fmaf(n1A, colo, accA[2 * p]));
            accA[2 * p + 1] = fmaf(n0A, cehi, fmaf(n1A, cohi, accA[2 * p + 1]));
            accB[2 * p]     = fmaf(n0B, celo, fmaf(n1B, colo, accB[2 * p]));
            accB[2 * p + 1] = fmaf(n0B, cehi, fmaf(n1B, cohi, accB[2 * p + 1]));
        }
    }

#pragma unroll
    for (int off = 16; off > 0; off >>= 1)
#pragma unroll
        for (int c = 0; c < NC; ++c) {
            accA[c] += __shfl_xor_sync(0xffffffffu, accA[c], off);
            accB[c] += __shfl_xor_sync(0xffffffffu, accB[c], off);
        }

    // acc is on normalized fn: out = (acc + MU*tot*inv) * sx
    if (lane < NC)
        out[(size_t)bA * NC + lane] = (accA[lane] + MU * totA * invA) * sxA;
    else if (lane >= 16 && lane < 16 + NC)
        out[(size_t)bB * NC + (lane - 16)] =
            (accB[lane - 16] + MU * totB * invB) * sxB;
}

// ---------------------------------------------------------------------------
extern "C" void kernel_launch(void* const* d_in, const int* in_sizes, int n_in,
                              void* d_out, int out_size) {
    const float* x       = (const float*)d_in[0];
    const float* centers = (const float*)d_in[1];
    const float* widths  = (const float*)d_in[2];
    const float* cons    = (const float*)d_in[3];
    const int*   rules   = (const int*)d_in[4];
    float* out = (float*)d_out;

    const long long TOTAL = (long long)NB_B * NC + (long long)NB_B * NR +
                            (long long)NB_B * NDP1;

    float* out_p = out;
    float* norm_p;
    float* xext_p = out;
    int write_xext = 0;

    if ((long long)out_size == TOTAL) {
        norm_p = out + (size_t)NB_B * NC;
        xext_p = out + (size_t)NB_B * NC + (size_t)NB_B * NR;
        write_xext = 1;
    } else {
        void* sp = nullptr;
        cudaGetSymbolAddress(&sp, g_norm_scratch);
        norm_p = (float*)sp;
    }

    prep_kernel<<<NR / 16, 256>>>(cons, rules, centers, widths);
    gemm_kernel<<<dim3(NB_B / 64, 16), 256>>>(x, norm_p);
    finalize_kernel<<<NB_B / 16, 256>>>(x, norm_p, xext_p, out_p, write_xext);
}

// round 17
// speedup vs baseline: 2.3649x; 2.3649x over previous
#include <cuda_runtime.h>
#include <cuda_bf16.h>
#include <cstdint>

#define NB_B 4096
#define ND 16
#define NM 4
#define NR 2048
#define NC 10
#define NDP1 17
#define MU 8.5f
#define LOG2E 1.4426950408889634f

// cons planes, mean-centered bf16x2, pair-interleaved for LDG.128:
//   g_consA[q] = {p0/even, p0/odd, p1/even, p1/odd}
//   g_consB[q] = {p2/even, p2/odd, p3/even, p3/odd}
//   g_consC[q] = {p4/even, p4/odd}
__device__ uint4    g_consA[NR / 2];
__device__ uint4    g_consB[NR / 2];
__device__ uint2    g_consC[NR / 2];
__device__ unsigned g_rpack[NR];                        // 16 dims x 2 bits
__device__ float    g_norm_scratch[(size_t)NB_B * NR];  // fallback only

__device__ __forceinline__ float bf16lo(unsigned w) {
    return __uint_as_float(w << 16);
}
__device__ __forceinline__ float bf16hi(unsigned w) {
    return __uint_as_float(w & 0xffff0000u);
}
__device__ __forceinline__ float ex2(float s) {
    float r;
    asm("ex2.approx.ftz.f32 %0, %1;" : "=f"(r) : "f"(s));
    return r;
}

// sum of 8 batch-paired table entries selected by the 16 2-bit fields of u
__device__ __forceinline__ float2 lookup8(const float2 (*tab)[16], unsigned u) {
    float2 r = tab[0][u & 15];
#pragma unroll
    for (int t = 1; t < 8; ++t) {
        float2 a = tab[t][(u >> (4 * t)) & 15];
        r.x += a.x;
        r.y += a.y;
    }
    return r;
}

// ---------------------------------------------------------------------------
// K0: coalesced prep. 128 blocks x 256 thr; 16 rules/block (R10-proven).
// ---------------------------------------------------------------------------
__global__ __launch_bounds__(256) void prep_kernel(
    const float* __restrict__ cons, const int* __restrict__ rules) {
    __shared__ float sc[16 * NDP1 * NC];   // 10880 B
    __shared__ int   sr[16 * ND];

    const int tid = threadIdx.x;
    const int r0  = blockIdx.x * 16;

    const float* cbase = cons + (size_t)r0 * NDP1 * NC;
#pragma unroll
    for (int i = tid; i < 16 * NDP1 * NC; i += 256) sc[i] = cbase[i];
    sr[tid] = rules[r0 * ND + tid];        // exactly 256 ints
    __syncthreads();

    if (tid < 80) {
        const int rl = tid / 5, p = tid % 5;
        const float* row = sc + rl * NDP1 * NC + 2 * p;
        float s0 = 0.f, s1 = 0.f;
#pragma unroll
        for (int j = 0; j < NDP1; ++j) {
            s0 += row[j * NC];
            s1 += row[j * NC + 1];
        }
        const int gw = r0 + rl, q = gw >> 1, r1 = gw & 1;
        __nv_bfloat162 h = __floats2bfloat162_rn(s0 - MU, s1 - MU);
        unsigned wb = *(unsigned*)&h;
        if (p == 0)      ((unsigned*)g_consA)[q * 4 + 0 + r1] = wb;
        else if (p == 1) ((unsigned*)g_consA)[q * 4 + 2 + r1] = wb;
        else if (p == 2) ((unsigned*)g_consB)[q * 4 + 0 + r1] = wb;
        else if (p == 3) ((unsigned*)g_consB)[q * 4 + 2 + r1] = wb;
        else             ((unsigned*)g_consC)[q * 2 + r1]     = wb;
    } else if (tid < 96) {
        const int rl = tid - 80;
        unsigned pk = 0;
#pragma unroll
        for (int d = 0; d < ND; ++d)
            pk |= ((unsigned)sr[rl * ND + d] & 3u) << (2 * d);
        g_rpack[r0 + rl] = pk;
    }
}

// ---------------------------------------------------------------------------
// K1 (fused, scalar FMA, f in REGISTERS): 128 thr = 4 warps = one batch-pair.
// Tables hold log2-memberships (LOG2E folded) -> bare EX2 per rule.
// PASS 1: lookups, ex2, f -> registers, scalar bf16 cons GEMV on
// unnormalized f. Reduce -> tot/inv. PASS 2: STG fn = f*inv from registers.
// No f-park smem, no scale kernel.
// ---------------------------------------------------------------------------
__global__ __launch_bounds__(128, 7) void fused_kernel(
    const float* __restrict__ x,
    const float* __restrict__ centers,
    const float* __restrict__ widths,
    float* __restrict__ norm_out,
    float* __restrict__ xext_out,
    float* __restrict__ out,
    int write_xext) {
    __shared__ float  s_e[2][64];
    __shared__ float2 s_tab[8][16];      // [table][idx] = (eA, eB), log2 scale
    __shared__ float  s_sum[4][2];
    __shared__ float  s_acc[4][2][NC];
    __shared__ float  s_sx[2];

    const int tid  = threadIdx.x;
    const int w    = tid >> 5;
    const int lane = tid & 31;
    const int bA   = blockIdx.x * 2;
    const int bB   = bA + 1;

    // setup: warps 0,1 build per-batch tables (warp h -> component h)
    if (w < 2) {
        const int b = bA + w;
        float xv = (lane < ND) ? x[b * ND + lane] : 0.f;
        float sx = xv;
#pragma unroll
        for (int off = 16; off > 0; off >>= 1)
            sx += __shfl_xor_sync(0xffffffffu, sx, off);
        sx += 1.f;
        if (lane == 0) s_sx[w] = sx;
        if (write_xext) {
            if (lane < ND) xext_out[b * NDP1 + lane] = xv;
            if (lane == ND) xext_out[b * NDP1 + ND] = 1.f;
        }
#pragma unroll
        for (int k = lane; k < 64; k += 32) {
            int d = k >> 2, m = k & 3;
            float c  = centers[d * NM + m];
            float wd = widths[d * NM + m];
            float xd = __shfl_sync(0xffffffffu, xv, d);
            float dx = xd - c;
            // log2-scale: e = -dx^2/(2 wd^2) * LOG2E
            s_e[w][k] = -(dx * dx) * (0.5f * LOG2E) / (wd * wd);
        }
        __syncwarp();
#pragma unroll
        for (int k = lane; k < 128; k += 32) {
            int t = k >> 4, i = k & 15;
            float v = s_e[w][(2 * t) * 4 + (i & 3)] +
                      s_e[w][(2 * t + 1) * 4 + (i >> 2)];
            if (w == 0) s_tab[t][i].x = v;
            else        s_tab[t][i].y = v;
        }
    }
    __syncthreads();

    const uint2* __restrict__ rp = (const uint2*)g_rpack;

    float accA[NC], accB[NC];
#pragma unroll
    for (int c = 0; c < NC; ++c) { accA[c] = 0.f; accB[c] = 0.f; }
    float sumA = 0.f, sumB = 0.f;
    float fA[16], fB[16];                 // f stays in registers

    // ---- PASS 1: lookups, ex2, GEMV on unnormalized f ----
#pragma unroll
    for (int k = 0; k < 8; ++k) {
        const int q = (w * 8 + k) * 32 + lane;    // rule-pair index
        uint2 pp = rp[q];
        float2 s0 = lookup8(s_tab, pp.x);
        float2 s1 = lookup8(s_tab, pp.y);
        float f0A = ex2(s0.x), f1A = ex2(s1.x);
        float f0B = ex2(s0.y), f1B = ex2(s1.y);
        sumA += f0A + f1A;
        sumB += f0B + f1B;
        fA[2 * k] = f0A; fA[2 * k + 1] = f1A;
        fB[2 * k] = f0B; fB[2 * k + 1] = f1B;

        uint4 cA = g_consA[q];
        uint4 cB = g_consB[q];
        uint2 cC = g_consC[q];
        const unsigned we[5] = {cA.x, cA.z, cB.x, cB.z, cC.x};
        const unsigned wo[5] = {cA.y, cA.w, cB.y, cB.w, cC.y};
#pragma unroll
        for (int p = 0; p < 5; ++p) {
            const float celo = bf16lo(we[p]), cehi = bf16hi(we[p]);
            const float colo = bf16lo(wo[p]), cohi = bf16hi(wo[p]);
            accA[2 * p]     = fmaf(f0A, celo, fmaf(f1A, colo, accA[2 * p]));
            accA[2 * p + 1] = fmaf(f0A, cehi, fmaf(f1A, cohi, accA[2 * p + 1]));
            accB[2 * p]     = fmaf(f0B, celo, fmaf(f1B, colo, accB[2 * p]));
            accB[2 * p + 1] = fmaf(f0B, cehi, fmaf(f1B, cohi, accB[2 * p + 1]));
        }
    }

#pragma unroll
    for (int off = 16; off > 0; off >>= 1) {
        sumA += __shfl_xor_sync(0xffffffffu, sumA, off);
        sumB += __shfl_xor_sync(0xffffffffu, sumB, off);
#pragma unroll
        for (int c = 0; c < NC; ++c) {
            accA[c] += __shfl_xor_sync(0xffffffffu, accA[c], off);
            accB[c] += __shfl_xor_sync(0xffffffffu, accB[c], off);
        }
    }
    if (lane == 0) {
        s_sum[w][0] = sumA;
        s_sum[w][1] = sumB;
#pragma unroll
        for (int c = 0; c < NC; ++c) {
            s_acc[w][0][c] = accA[c];
            s_acc[w][1][c] = accB[c];
        }
    }
    __syncthreads();

    const float totA = s_sum[0][0] + s_sum[1][0] + s_sum[2][0] + s_sum[3][0];
    const float totB = s_sum[0][1] + s_sum[1][1] + s_sum[2][1] + s_sum[3][1];
    const float invA = 1.f / (totA + 1e-9f);
    const float invB = 1.f / (totB + 1e-9f);

    // ---- PASS 2: STG normalized f from registers ----
    float2* npA = (float2*)(norm_out + (size_t)bA * NR);
    float2* npB = (float2*)(norm_out + (size_t)bB * NR);
#pragma unroll
    for (int k = 0; k < 8; ++k) {
        const int q = (w * 8 + k) * 32 + lane;
        npA[q] = make_float2(fA[2 * k] * invA, fA[2 * k + 1] * invA);
        npB[q] = make_float2(fB[2 * k] * invB, fB[2 * k + 1] * invB);
    }

    // ---- output: acc on unnormalized f -> (a + MU*tot)*inv*sx ----
    if (tid < 20) {
        const int h = tid / 10, c = tid % 10;
        float a = s_acc[0][h][c] + s_acc[1][h][c] +
                  s_acc[2][h][c] + s_acc[3][h][c];
        float tot = h ? totB : totA;
        float inv = h ? invB : invA;
        out[(size_t)(bA + h) * NC + c] = (a + MU * tot) * inv * s_sx[h];
    }
}

// ---------------------------------------------------------------------------
extern "C" void kernel_launch(void* const* d_in, const int* in_sizes, int n_in,
                              void* d_out, int out_size) {
    const float* x       = (const float*)d_in[0];
    const float* centers = (const float*)d_in[1];
    const float* widths  = (const float*)d_in[2];
    const float* cons    = (const float*)d_in[3];
    const int*   rules   = (const int*)d_in[4];
    float* out = (float*)d_out;

    const long long TOTAL = (long long)NB_B * NC + (long long)NB_B * NR +
                            (long long)NB_B * NDP1;

    float* out_p = out;
    float* norm_p;
    float* xext_p = out;
    int write_xext = 0;

    if ((long long)out_size == TOTAL) {
        norm_p = out + (size_t)NB_B * NC;
        xext_p = out + (size_t)NB_B * NC + (size_t)NB_B * NR;
        write_xext = 1;
    } else {
        void* sp = nullptr;
        cudaGetSymbolAddress(&sp, g_norm_scratch);
        norm_p = (float*)sp;
    }

    prep_kernel<<<NR / 16, 256>>>(cons, rules);
    fused_kernel<<<NB_B / 2, 128>>>(x, centers, widths, norm_p,
                                    xext_p, out_p, write_xext);
}